// round 11
// baseline (speedup 1.0000x reference)
#include <cuda_runtime.h>
#include <cstddef>

// Problem constants (fixed shapes from setup_inputs)
#define C_    32
#define H_    192
#define W_    256
#define S_    9
#define G_    8
#define HW_   (H_*W_)            // 49152
#define HWS_  ((size_t)HW_*S_)   // 442368
#define CHWS_ ((size_t)C_*HWS_)

#define TPB_A 64                 // att kernel: pixels per CTA
#define TPB_B 128                // stream kernel: pixels per CTA
#define NSPL  2                  // source-image split across blockIdx.y
#define NPER  (8/NSPL)           // images per CTA

__device__ float g_att[S_ * HW_];   // att scratch, SoA: [s][p] (coalesced)

// ---------------- kernel A: attention weights (prep folded in) ----------------
// tv = Wp^T (Wp rm + bp): no precomputed M needed. Ref rows staged via float4.
__global__ void __launch_bounds__(TPB_A, 8)
att_kernel(const float* __restrict__ f, const float* __restrict__ Wp,
           const float* __restrict__ bp) {
    __shared__ float  Wsm[C_*C_];        // Wp, row-major [d][c]
    __shared__ float4 rstg[TPB_A*S_/4];  // 64 px * 9 floats = 144 float4

    const int tid = threadIdx.x;
    const int p0  = blockIdx.x * TPB_A;
    const int p   = p0 + tid;

    // stage Wp (256 float4, 4 per thread)
    {
        float4* W4 = (float4*)Wsm;
        const float4* Wg = (const float4*)Wp;
        #pragma unroll
        for (int k = 0; k < 4; k++) W4[tid + TPB_A*k] = Wg[tid + TPB_A*k];
    }
    __syncthreads();

    // rm gather (strided scalar, small: 32 loads)
    float rm[C_];
    #pragma unroll
    for (int c = 0; c < C_; c++) rm[c] = __ldg(f + (size_t)c*HWS_ + (size_t)p*S_ + 4);

    // u = Wp rm + bp   (row reads: uniform address -> broadcast, conflict-free)
    float u[C_];
    #pragma unroll
    for (int d = 0; d < C_; d++) {
        float a = __ldg(bp + d);
        const float* row = Wsm + d*C_;
        #pragma unroll
        for (int c = 0; c < C_; c++) a += row[c] * rm[c];
        u[d] = a;
    }
    // tv[c] = sum_d u[d] * Wp[d][c]  (uniform address -> broadcast)
    float tv[C_];
    #pragma unroll
    for (int c = 0; c < C_; c++) {
        float a = 0.f;
        #pragma unroll
        for (int d = 0; d < C_; d++) a += u[d] * Wsm[d*C_ + c];
        tv[c] = a;
    }

    // logits via staged ref tiles
    float l[S_];
    #pragma unroll
    for (int s = 0; s < S_; s++) l[s] = 0.f;

    #pragma unroll 1
    for (int c = 0; c < C_; c++) {
        __syncthreads();
        const float4* rs = (const float4*)(f + (size_t)c*HWS_ + (size_t)p0*S_);
        rstg[tid]        = rs[tid];
        rstg[tid+TPB_A]  = rs[tid+TPB_A];
        if (tid < 16) rstg[tid+2*TPB_A] = rs[tid+2*TPB_A];
        __syncthreads();
        const float* r = (const float*)rstg + tid*S_;   // 9-float stride: conflict-free
        const float t = tv[c];
        #pragma unroll
        for (int s = 0; s < S_; s++) l[s] += t * r[s];
    }

    // softmax (shift-invariant terms dropped)
    const float inv_sqrtC = 0.17677669529663687f;   // 1/sqrt(32)
    float mx = l[0];
    #pragma unroll
    for (int s = 1; s < S_; s++) mx = fmaxf(mx, l[s]);
    float e[S_], sum = 0.f;
    #pragma unroll
    for (int s = 0; s < S_; s++) { e[s] = __expf((l[s] - mx) * inv_sqrtC); sum += e[s]; }
    const float isum = __frcp_rn(sum);
    #pragma unroll
    for (int s = 0; s < S_; s++) g_att[s * HW_ + p] = e[s] * isum;
}

// ---------------- kernel B: stream sources via cooperative float4 staging ----------------
// Per channel: 5 tiles (ref + NPER src) staged with LDG.128 (perfect coalescing),
// consumed from SMEM at 9-float stride (gcd(9,32)=1 -> conflict-free).
__global__ void __launch_bounds__(TPB_B, 6)
stream_kernel(const float* __restrict__ f, float* __restrict__ out) {
    __shared__ float4 stg[(1+NPER) * (TPB_B*S_/4)];   // 5 * 288 float4 = 23 KB

    const int tid = threadIdx.x;
    const int p0  = blockIdx.x * TPB_B;
    const int p   = p0 + tid;
    const int n0  = blockIdx.y * NPER;
    const float* sf = (const float*)stg;

    float att[S_];
    #pragma unroll
    for (int s = 0; s < S_; s++) att[s] = __ldg(&g_att[s * HW_ + p]);

    #pragma unroll 1
    for (int g = 0; g < G_; g++) {
        float acc[NPER];
        #pragma unroll
        for (int n = 0; n < NPER; n++) acc[n] = 0.f;

        #pragma unroll 1
        for (int cc = 0; cc < 4; cc++) {
            const int c = g*4 + cc;
            __syncthreads();   // previous tile fully consumed
            // stage ref tile (288 float4)
            {
                const float4* rs = (const float4*)(f + (size_t)c*HWS_ + (size_t)p0*S_);
                stg[tid]          = rs[tid];
                stg[tid+TPB_B]    = rs[tid+TPB_B];
                if (tid < 32) stg[tid+2*TPB_B] = rs[tid+2*TPB_B];
            }
            // stage NPER src tiles (evict-first: streamed once)
            #pragma unroll
            for (int n = 0; n < NPER; n++) {
                const float4* ss = (const float4*)(f + (size_t)(n0+n+1)*CHWS_
                                                     + (size_t)c*HWS_ + (size_t)p0*S_);
                float4* d = stg + (1+n)*(TPB_B*S_/4);
                d[tid]          = __ldcs(ss + tid);
                d[tid+TPB_B]    = __ldcs(ss + tid + TPB_B);
                if (tid < 32) d[tid+2*TPB_B] = __ldcs(ss + tid + 2*TPB_B);
            }
            __syncthreads();

            float w[S_];
            #pragma unroll
            for (int s = 0; s < S_; s++) w[s] = sf[tid*S_ + s] * att[s];
            #pragma unroll
            for (int n = 0; n < NPER; n++) {
                const float* sn = sf + (1+n)*(TPB_B*S_) + tid*S_;
                float a = 0.f;
                #pragma unroll
                for (int s = 0; s < S_; s++) a += w[s] * sn[s];
                acc[n] += a;
            }
        }
        #pragma unroll
        for (int n = 0; n < NPER; n++)
            out[(size_t)((n0 + n)*G_ + g)*HW_ + p] = acc[n];
    }
}

extern "C" void kernel_launch(void* const* d_in, const int* in_sizes, int n_in,
                              void* d_out, int out_size) {
    // Identify inputs by element count: f = 127401984, Wp = 1024, bp = 32
    const float* f  = nullptr;
    const float* Wp = nullptr;
    const float* bp = nullptr;
    for (int i = 0; i < n_in; i++) {
        if      (in_sizes[i] == 127401984) f  = (const float*)d_in[i];
        else if (in_sizes[i] == 1024)      Wp = (const float*)d_in[i];
        else if (in_sizes[i] == 32)        bp = (const float*)d_in[i];
    }
    if (!f || !Wp || !bp) {  // fallback positional
        f  = (const float*)d_in[0];
        Wp = (const float*)d_in[1];
        bp = (const float*)d_in[2];
    }
    float* out = (float*)d_out;

    att_kernel<<<HW_/TPB_A, TPB_A>>>(f, Wp, bp);
    dim3 gridB(HW_/TPB_B, NSPL);
    stream_kernel<<<gridB, TPB_B>>>(f, out);
}